// round 8
// baseline (speedup 1.0000x reference)
#include <cuda_runtime.h>
#include <math.h>

#define NB 4
#define NS 512
#define NDIM 512
#define NH 8
#define NDH 64
#define NM (NB*NS)     // 2048

// ---------------- device scratch (no allocations allowed) ----------------
__device__ float g_q[NB*NH*NS*NDH];     // [b][h][s][d]
__device__ float g_k[NB*NH*NS*NDH];
__device__ float g_v[NB*NH*NS*NDH];
__device__ float g_u[NB*NS*NH];
__device__ float g_w[NB*NH*NS];
__device__ float g_opos[NB*NH*NDH];     // [b][h][d] : w @ V
__device__ float g_y[NM*NDIM];

// tf32 hi/lo pre-split fragment arrays (dense GEMMs)
__device__ float g_xh[NM*NDIM], g_xl[NM*NDIM];
__device__ float g_yh[NM*NDIM], g_yl[NM*NDIM];
__device__ float g_wh[4*NDIM*NDIM], g_wl[4*NDIM*NDIM];
// attention fragment arrays
// Q A-side: [bh][mblk(32)][kblk(8)][lane(32)][reg(4)]
__device__ float g_qfh[NB*NH*NS*NDH], g_qfl[NB*NH*NS*NDH];
// K B-side: [bh][kblk(8 dims)][nblk(64 pos)][lane(32)][reg(2)]
__device__ float g_kfh[NB*NH*NS*NDH], g_kfl[NB*NH*NS*NDH];
// V B-side: [bh][kposblk(64)][nblk(8 dh)][lane(32)][reg(2)]
__device__ float g_vfh[NB*NH*NS*NDH], g_vfl[NB*NH*NS*NDH];

__device__ __forceinline__ unsigned f2tf(float x) {
    unsigned r;
    asm("cvt.rna.tf32.f32 %0, %1;" : "=r"(r) : "f"(x));
    return r;
}

__device__ __forceinline__ void mma_tf32(float (&d)[4], const unsigned (&a)[4],
                                         unsigned b0, unsigned b1) {
    asm volatile(
        "mma.sync.aligned.m16n8k8.row.col.f32.tf32.tf32.f32 "
        "{%0,%1,%2,%3}, {%4,%5,%6,%7}, {%8,%9}, {%0,%1,%2,%3};"
        : "+f"(d[0]), "+f"(d[1]), "+f"(d[2]), "+f"(d[3])
        : "r"(a[0]), "r"(a[1]), "r"(a[2]), "r"(a[3]), "r"(b0), "r"(b1));
}

__device__ __forceinline__ unsigned cvta_sh(const void* p) {
    return (unsigned)__cvta_generic_to_shared(p);
}
#define CPA16(dst, src) \
    asm volatile("cp.async.cg.shared.global [%0], [%1], 16;" :: "r"(dst), "l"(src))

// ---------------- coalesced split kernels (dense GEMM operands) ----------
__device__ __forceinline__ void split_a2(const float* __restrict__ src,
                                         float* __restrict__ dh, float* __restrict__ dl) {
    int gw = blockIdx.x * 8 + (threadIdx.x >> 5);
    int lane = threadIdx.x & 31;
    int mblk = gw >> 6, kblk = gw & 63;
    float h[4], l[4];
    #pragma unroll
    for (int r = 0; r < 4; r++) {
        int mr = (lane >> 2) | ((r & 1) << 3);
        int kc = (lane & 3) | ((r >> 1) << 2);
        float v = src[(mblk * 16 + mr) * NDIM + kblk * 8 + kc];
        h[r] = __uint_as_float(f2tf(v));
        l[r] = __uint_as_float(f2tf(v - h[r]));
    }
    int idx = (gw * 32 + lane) * 4;
    *(float4*)&dh[idx] = make_float4(h[0], h[1], h[2], h[3]);
    *(float4*)&dl[idx] = make_float4(l[0], l[1], l[2], l[3]);
}
__global__ void split_x_kernel(const float* __restrict__ X) { split_a2(X, g_xh, g_xl); }
__global__ void split_y_kernel() { split_a2(g_y, g_yh, g_yl); }

__global__ void split_w_kernel(const float* __restrict__ Wq, const float* __restrict__ Wk,
                               const float* __restrict__ Wv, const float* __restrict__ Wo) {
    int gw = blockIdx.x * 8 + (threadIdx.x >> 5);
    int lane = threadIdx.x & 31;
    int mat = gw >> 12;
    int rem = gw & 4095;
    int kblk = rem >> 6, nblk = rem & 63;
    const float* W = (mat == 0) ? Wq : (mat == 1) ? Wk : (mat == 2) ? Wv : Wo;
    int nc = lane >> 2, tl = lane & 3;
    float h[2], l[2];
    #pragma unroll
    for (int r = 0; r < 2; r++) {
        int kc = tl | (r << 2);
        float v = W[(kblk * 8 + kc) * NDIM + nblk * 8 + nc];
        h[r] = __uint_as_float(f2tf(v));
        l[r] = __uint_as_float(f2tf(v - h[r]));
    }
    int idx = mat * NDIM * NDIM + (rem * 32 + lane) * 2;
    *(float2*)&g_wh[idx] = make_float2(h[0], h[1]);
    *(float2*)&g_wl[idx] = make_float2(l[0], l[1]);
}

// ---------------- attention fragment splits ----------------
// Q A-side fragments (per bh): coalesced float4 writes per lane.
__global__ void split_q_kernel() {
    int gw = blockIdx.x * 8 + (threadIdx.x >> 5);   // 0..8191
    int lane = threadIdx.x & 31;
    int bh = gw >> 8, rem = gw & 255;
    int mblk = rem >> 3, kblk = rem & 7;
    const float* Q = g_q + (size_t)bh * NS * NDH;
    int g = lane >> 2, t = lane & 3;
    float h[4], l[4];
    #pragma unroll
    for (int r = 0; r < 4; r++) {
        int mr = g | ((r & 1) << 3);
        int kc = t | ((r >> 1) << 2);
        float v = Q[(mblk * 16 + mr) * NDH + kblk * 8 + kc];
        h[r] = __uint_as_float(f2tf(v));
        l[r] = __uint_as_float(f2tf(v - h[r]));
    }
    size_t idx = ((size_t)gw * 32 + lane) * 4;
    *(float4*)&g_qfh[idx] = make_float4(h[0], h[1], h[2], h[3]);
    *(float4*)&g_qfl[idx] = make_float4(l[0], l[1], l[2], l[3]);
}

// K and V B-side fragments (per bh)
__global__ void split_kv_kernel() {
    int gw = blockIdx.x * 8 + (threadIdx.x >> 5);   // 0..16383
    int lane = threadIdx.x & 31;
    int nc = lane >> 2, t = lane & 3;
    int bh = gw >> 9, rem = gw & 511;
    if (blockIdx.y == 0) {
        // K: [bh][kblk(8)][nblk(64)][lane][2]; value K[pos=nblk*8+nc][dim=kblk*8+t+4r]
        int kblk = rem >> 6, nblk = rem & 63;
        const float* K = g_k + (size_t)bh * NS * NDH;
        float h[2], l[2];
        #pragma unroll
        for (int r = 0; r < 2; r++) {
            float v = K[(nblk * 8 + nc) * NDH + kblk * 8 + t + 4 * r];
            h[r] = __uint_as_float(f2tf(v));
            l[r] = __uint_as_float(f2tf(v - h[r]));
        }
        size_t idx = ((size_t)gw * 32 + lane) * 2;
        *(float2*)&g_kfh[idx] = make_float2(h[0], h[1]);
        *(float2*)&g_kfl[idx] = make_float2(l[0], l[1]);
    } else {
        // V: [bh][kposblk(64)][nblk(8)][lane][2]; value V[kpos=kposblk*8+t+4r][dh=nblk*8+nc]
        int kposblk = rem >> 3, nblk = rem & 7;
        const float* V = g_v + (size_t)bh * NS * NDH;
        float h[2], l[2];
        #pragma unroll
        for (int r = 0; r < 2; r++) {
            float v = V[(kposblk * 8 + t + 4 * r) * NDH + nblk * 8 + nc];
            h[r] = __uint_as_float(f2tf(v));
            l[r] = __uint_as_float(f2tf(v - h[r]));
        }
        size_t idx = ((size_t)gw * 32 + lane) * 2;
        *(float2*)&g_vfh[idx] = make_float2(h[0], h[1]);
        *(float2*)&g_vfl[idx] = make_float2(l[0], l[1]);
    }
}

// =====================================================================
// tf32 x3 MMA GEMM, 128x128 tile, 8 warps, cp.async double-buffered smem.
// =====================================================================
__device__ __forceinline__ void mma_gemm_tile2(const float* __restrict__ Ah,
                                               const float* __restrict__ Al,
                                               const float* __restrict__ Bh,
                                               const float* __restrict__ Bl,
                                               int mblk0, int nblk0,
                                               float (&acc)[2][8][4], float* sm) {
    float* sAh = sm;
    float* sAl = sm + 2048;
    float* sBh = sm + 4096;
    float* sBl = sm + 6144;
    int tid = threadIdx.x, lane = tid & 31, wid = tid >> 5;
    int warp_m = wid >> 1, warp_n = wid & 1;
    int a_mblk = tid >> 5, a_lane = tid & 31;
    int b_nblk = tid >> 4, b_pair = (tid & 15) * 2;

    unsigned dAh = cvta_sh(&sAh[a_mblk * 128 + a_lane * 4]);
    unsigned dAl = cvta_sh(&sAl[a_mblk * 128 + a_lane * 4]);
    unsigned dBh = cvta_sh(&sBh[b_nblk * 64 + b_pair * 2]);
    unsigned dBl = cvta_sh(&sBl[b_nblk * 64 + b_pair * 2]);
    const float* srcAh = &Ah[((mblk0 + a_mblk) * 64) * 128 + a_lane * 4];
    const float* srcAl = &Al[((mblk0 + a_mblk) * 64) * 128 + a_lane * 4];
    const float* srcBh = &Bh[(nblk0 + b_nblk) * 64 + b_pair * 2];
    const float* srcBl = &Bl[(nblk0 + b_nblk) * 64 + b_pair * 2];

    auto issue = [&](int kb, int buf) {
        CPA16(dAh + buf * 4096, srcAh + kb * 128);
        CPA16(dAl + buf * 4096, srcAl + kb * 128);
        CPA16(dBh + buf * 4096, srcBh + (size_t)kb * 64 * 64);
        CPA16(dBl + buf * 4096, srcBl + (size_t)kb * 64 * 64);
        asm volatile("cp.async.commit_group;");
    };

    issue(0, 0);
    int buf = 0;
    for (int kb = 0; kb < 64; kb++) {
        if (kb < 63) {
            issue(kb + 1, buf ^ 1);
            asm volatile("cp.async.wait_group 1;");
        } else {
            asm volatile("cp.async.wait_group 0;");
        }
        __syncthreads();

        unsigned ah[2][4], al[2][4];
        #pragma unroll
        for (int mb2 = 0; mb2 < 2; mb2++) {
            float4 h4 = *(float4*)&sAh[buf * 1024 + (warp_m * 2 + mb2) * 128 + lane * 4];
            float4 l4 = *(float4*)&sAl[buf * 1024 + (warp_m * 2 + mb2) * 128 + lane * 4];
            ah[mb2][0] = __float_as_uint(h4.x); ah[mb2][1] = __float_as_uint(h4.y);
            ah[mb2][2] = __float_as_uint(h4.z); ah[mb2][3] = __float_as_uint(h4.w);
            al[mb2][0] = __float_as_uint(l4.x); al[mb2][1] = __float_as_uint(l4.y);
            al[mb2][2] = __float_as_uint(l4.z); al[mb2][3] = __float_as_uint(l4.w);
        }
        #pragma unroll
        for (int nb = 0; nb < 8; nb++) {
            float2 h2 = *(float2*)&sBh[buf * 1024 + (warp_n * 8 + nb) * 64 + lane * 2];
            float2 l2 = *(float2*)&sBl[buf * 1024 + (warp_n * 8 + nb) * 64 + lane * 2];
            unsigned b0h = __float_as_uint(h2.x), b1h = __float_as_uint(h2.y);
            unsigned b0l = __float_as_uint(l2.x), b1l = __float_as_uint(l2.y);
            #pragma unroll
            for (int mb2 = 0; mb2 < 2; mb2++) {
                mma_tf32(acc[mb2][nb], ah[mb2], b0h, b1h);
                mma_tf32(acc[mb2][nb], ah[mb2], b0l, b1l);
                mma_tf32(acc[mb2][nb], al[mb2], b0h, b1h);
            }
        }
        __syncthreads();
        buf ^= 1;
    }
}

__global__ void __launch_bounds__(256, 2)
qkv_mma() {
    __shared__ float sm[8192];
    int mat = blockIdx.z;
    float* out = (mat == 0) ? g_q : (mat == 1) ? g_k : g_v;
    const float* Bh = g_wh + mat * NDIM * NDIM;
    const float* Bl = g_wl + mat * NDIM * NDIM;
    int m0 = blockIdx.y * 128, n0 = blockIdx.x * 128;
    float acc[2][8][4] = {};
    mma_gemm_tile2(g_xh, g_xl, Bh, Bl, m0 >> 4, n0 >> 3, acc, sm);

    int lane = threadIdx.x & 31, wid = threadIdx.x >> 5;
    int warp_m = wid >> 1, warp_n = wid & 1;
    int g = lane >> 2, t = lane & 3;
    #pragma unroll
    for (int mb2 = 0; mb2 < 2; mb2++) {
        int mrow = m0 + warp_m * 32 + mb2 * 16 + g;
        #pragma unroll
        for (int nb = 0; nb < 8; nb++) {
            int ncol = n0 + (warp_n * 8 + nb) * 8 + 2 * t;
            int h = ncol >> 6, d = ncol & 63;
            {
                int b = mrow >> 9, s = mrow & 511;
                *(float2*)&out[((b * NH + h) * NS + s) * NDH + d] =
                    make_float2(acc[mb2][nb][0], acc[mb2][nb][1]);
            }
            {
                int m2 = mrow + 8;
                int b = m2 >> 9, s = m2 & 511;
                *(float2*)&out[((b * NH + h) * NS + s) * NDH + d] =
                    make_float2(acc[mb2][nb][2], acc[mb2][nb][3]);
            }
        }
    }
}

__global__ void __launch_bounds__(256, 2)
out_mma(const float* __restrict__ bo, float* __restrict__ out) {
    __shared__ float sm[8192];
    const float* Bh = g_wh + 3 * NDIM * NDIM;
    const float* Bl = g_wl + 3 * NDIM * NDIM;
    int m0 = blockIdx.y * 128, n0 = blockIdx.x * 128;
    float acc[2][8][4] = {};
    mma_gemm_tile2(g_yh, g_yl, Bh, Bl, m0 >> 4, n0 >> 3, acc, sm);

    int lane = threadIdx.x & 31, wid = threadIdx.x >> 5;
    int warp_m = wid >> 1, warp_n = wid & 1;
    int g = lane >> 2, t = lane & 3;
    #pragma unroll
    for (int mb2 = 0; mb2 < 2; mb2++) {
        int mrow = m0 + warp_m * 32 + mb2 * 16 + g;
        #pragma unroll
        for (int nb = 0; nb < 8; nb++) {
            int ncol = n0 + (warp_n * 8 + nb) * 8 + 2 * t;
            float b0 = bo[ncol], b1 = bo[ncol + 1];
            *(float2*)&out[(size_t)mrow * NDIM + ncol] =
                make_float2(acc[mb2][nb][0] + b0, acc[mb2][nb][1] + b1);
            *(float2*)&out[(size_t)(mrow + 8) * NDIM + ncol] =
                make_float2(acc[mb2][nb][2] + b0, acc[mb2][nb][3] + b1);
        }
    }
}

// ---------------- tiny positional MLP ----------------
__global__ void u_kernel(const float* __restrict__ pos,
                         const float* __restrict__ Wp1, const float* __restrict__ bp1,
                         const float* __restrict__ Wp2, const float* __restrict__ bp2,
                         const float* __restrict__ Wh) {
    int idx = blockIdx.x * blockDim.x + threadIdx.x;
    if (idx >= NM) return;
    g_opos[idx & (NB*NH*NDH - 1)] = 0.0f;
    const float* pp = pos + idx * 3;
    float p0 = pp[0], p1 = pp[1], p2 = pp[2];
    float h1[3];
    #pragma unroll
    for (int j = 0; j < 3; j++)
        h1[j] = fmaxf(0.0f, p0 * Wp1[j] + p1 * Wp1[3 + j] + p2 * Wp1[6 + j] + bp1[j]);
    float u[NH];
    #pragma unroll
    for (int hh = 0; hh < NH; hh++) u[hh] = 0.0f;
    for (int j = 0; j < 64; j++) {
        float pv = h1[0] * Wp2[j] + h1[1] * Wp2[64 + j] + h1[2] * Wp2[128 + j] + bp2[j];
        #pragma unroll
        for (int hh = 0; hh < NH; hh++) u[hh] += pv * Wh[j * NH + hh];
    }
    #pragma unroll
    for (int hh = 0; hh < NH; hh++) g_u[idx * NH + hh] = u[hh];
}

__global__ void pos_w_kernel() {
    __shared__ float red[512];
    int bh = blockIdx.x;
    int b = bh >> 3, h = bh & 7;
    int k = threadIdx.x;
    float t = -g_u[(b * NS + k) * NH + h];
    red[k] = t; __syncthreads();
    for (int s = 256; s > 0; s >>= 1) { if (k < s) red[k] = fmaxf(red[k], red[k + s]); __syncthreads(); }
    float m = red[0]; __syncthreads();
    float e = expf(t - m);
    red[k] = e; __syncthreads();
    for (int s = 256; s > 0; s >>= 1) { if (k < s) red[k] += red[k + s]; __syncthreads(); }
    g_w[bh * NS + k] = e / red[0];
}

__global__ void opos_kernel() {
    __shared__ float part[4][64];
    int bh = blockIdx.x;
    int kq = blockIdx.y;
    int d = threadIdx.x & 63;
    int ks = threadIdx.x >> 6;
    const float* V = g_v + (size_t)bh * NS * NDH;
    const float* w = g_w + bh * NS;
    int kbase = kq * 128 + ks * 32;
    float s = 0.0f;
    #pragma unroll 4
    for (int k = kbase; k < kbase + 32; k++)
        s += w[k] * V[k * NDH + d];
    part[ks][d] = s;
    __syncthreads();
    if (threadIdx.x < 64)
        atomicAdd(&g_opos[bh * NDH + d], part[0][d] + part[1][d] + part[2][d] + part[3][d]);
}

// =====================================================================
// tf32 mma flash attention. 4 warps per (bh, 64-q tile), warp owns m16.
// No __syncthreads in the mainloop (P round-trip is warp-private).
// =====================================================================
__global__ void __launch_bounds__(128, 3)
attn_mma(const float* __restrict__ gate) {
    __shared__ float Ps[64][68];
    __shared__ float opos_s[64];
    int tid = threadIdx.x, lane = tid & 31, w = tid >> 5;
    int bh = blockIdx.y, q0 = blockIdx.x * 64;
    int h = bh & 7, b = bh >> 3;
    int g = lane >> 2, t = lane & 3;
    int mblk = (q0 >> 4) + w;
    int rowbase = w * 16;

    float gv = 1.0f / (1.0f + __expf(-gate[h]));
    float og = 1.0f - gv;
    if (tid < 64) opos_s[tid] = g_opos[bh * NDH + tid];
    __syncthreads();

    // Q fragments, hoisted (8 kblk x 4 regs, hi+lo)
    unsigned aqh[8][4], aql[8][4];
    {
        const float* qh = g_qfh + ((size_t)(bh * 32 + mblk) * 8) * 128;
        const float* ql = g_qfl + ((size_t)(bh * 32 + mblk) * 8) * 128;
        #pragma unroll
        for (int kb = 0; kb < 8; kb++) {
            float4 hv = *(const float4*)&qh[kb * 128 + lane * 4];
            float4 lv = *(const float4*)&ql[kb * 128 + lane * 4];
            aqh[kb][0] = __float_as_uint(hv.x); aqh[kb][1] = __float_as_uint(hv.y);
            aqh[kb][2] = __float_as_uint(hv.z); aqh[kb][3] = __float_as_uint(hv.w);
            aql[kb][0] = __float_as_uint(lv.x); aql[kb][1] = __float_as_uint(lv.y);
            aql[kb][2] = __float_as_uint(lv.z); aql[kb][3] = __float_as_uint(lv.w);
        }
    }

    const float* kfh = g_kfh + (size_t)bh * 8 * 64 * 64;
    const float* kfl = g_kfl + (size_t)bh * 8 * 64 * 64;
    const float* vfh = g_vfh + (size_t)bh * 64 * 8 * 64;
    const float* vfl = g_vfl + (size_t)bh * 64 * 8 * 64;

    float o[8][4] = {};
    float mrow[2] = {-1e30f, -1e30f};
    float lrow[2] = {0.0f, 0.0f};

    for (int kc = 0; kc < 8; kc++) {
        // ---- S chunk = Q K^T (64q x 64kpos), 3-split tf32 ----
        float sacc[8][4] = {};
        #pragma unroll
        for (int kb = 0; kb < 8; kb++) {
            #pragma unroll
            for (int nb = 0; nb < 8; nb++) {
                int nblkg = kc * 8 + nb;
                float2 h2 = *(const float2*)&kfh[((size_t)(kb * 64 + nblkg)) * 64 + lane * 2];
                float2 l2 = *(const float2*)&kfl[((size_t)(kb * 64 + nblkg)) * 64 + lane * 2];
                unsigned b0h = __float_as_uint(h2.x), b1h = __float_as_uint(h2.y);
                unsigned b0l = __float_as_uint(l2.x), b1l = __float_as_uint(l2.y);
                mma_tf32(sacc[nb], aqh[kb], b0h, b1h);
                mma_tf32(sacc[nb], aqh[kb], b0l, b1l);
                mma_tf32(sacc[nb], aql[kb], b0h, b1h);
            }
        }
        // ---- online softmax on accumulators (rows g and g+8) ----
        #pragma unroll
        for (int j = 0; j < 2; j++) {
            float mx = -1e30f;
            #pragma unroll
            for (int nb = 0; nb < 8; nb++)
                mx = fmaxf(mx, fmaxf(sacc[nb][2*j], sacc[nb][2*j+1]));
            mx *= 0.125f;
            mx = fmaxf(mx, __shfl_xor_sync(0xFFFFFFFF, mx, 1));
            mx = fmaxf(mx, __shfl_xor_sync(0xFFFFFFFF, mx, 2));
            float mn = fmaxf(mrow[j], mx);
            float alpha = __expf(mrow[j] - mn);
            float rs = 0.0f;
            #pragma unroll
            for (int nb = 0; nb < 8; nb++) {
                float p0 = __expf(sacc[nb][2*j] * 0.125f - mn);
                float p1 = __expf(sacc[nb][2*j+1] * 0.125f - mn);
                sacc[nb][2*j] = p0; sacc[nb][2*j+1] = p1;
                rs += p0 + p1;
            }
            rs += __shfl_xor_sync(0xFFFFFFFF, rs, 1);
            rs += __shfl_xor_sync(0xFFFFFFFF, rs, 2);
            lrow[j] = lrow[j] * alpha + rs;
            mrow[j] = mn;
            #pragma unroll
            for (int nb = 0; nb < 8; nb++) { o[nb][2*j] *= alpha; o[nb][2*j+1] *= alpha; }
        }
        // ---- P c-layout -> warp-private smem strip ----
        __syncwarp();
        #pragma unroll
        for (int nb = 0; nb < 8; nb++) {
            *(float2*)&Ps[rowbase + g][nb * 8 + 2 * t]     = make_float2(sacc[nb][0], sacc[nb][1]);
            *(float2*)&Ps[rowbase + g + 8][nb * 8 + 2 * t] = make_float2(sacc[nb][2], sacc[nb][3]);
        }
        __syncwarp();
        // ---- O += P @ V (3-split) ----
        #pragma unroll
        for (int kb = 0; kb < 8; kb++) {
            int kposblk = kc * 8 + kb;
            float p0 = Ps[rowbase + g][kb * 8 + t];
            float p1 = Ps[rowbase + g + 8][kb * 8 + t];
            float p2 = Ps[rowbase + g][kb * 8 + t + 4];
            float p3 = Ps[rowbase + g + 8][kb * 8 + t + 4];
            unsigned ph[4], pl[4];
            ph[0] = f2tf(p0); pl[0] = f2tf(p0 - __uint_as_float(ph[0]));
            ph[1] = f2tf(p1); pl[1] = f2tf(p1 - __uint_as_float(ph[1]));
            ph[2] = f2tf(p2); pl[2] = f2tf(p2 - __uint_as_float(ph[2]));
            ph[3] = f2tf(p3); pl[3] = f2tf(p3 - __uint_as_float(ph[3]));
            #pragma unroll
            for (int nb = 0; nb < 8; nb++) {
                float2 h2 = *(const float2*)&vfh[((size_t)(kposblk * 8 + nb)) * 64 + lane * 2];
                float2 l2 = *(const float2*)&vfl[((size_t)(kposblk * 8 + nb)) * 64 + lane * 2];
                unsigned b0h = __float_as_uint(h2.x), b1h = __float_as_uint(h2.y);
                unsigned b0l = __float_as_uint(l2.x), b1l = __float_as_uint(l2.y);
                mma_tf32(o[nb], ph, b0h, b1h);
                mma_tf32(o[nb], ph, b0l, b1l);
                mma_tf32(o[nb], pl, b0h, b1h);
            }
        }
    }

    // ---- epilogue: out = og * o / l + gv * O_pos ----
    #pragma unroll
    for (int j = 0; j < 2; j++) {
        int q = q0 + rowbase + g + j * 8;
        float f = og / lrow[j];
        #pragma unroll
        for (int nb = 0; nb < 8; nb++) {
            int d = nb * 8 + 2 * t;
            *(float2*)&g_y[((size_t)b * NS + q) * NDIM + h * NDH + d] =
                make_float2(o[nb][2*j] * f + gv * opos_s[d],
                            o[nb][2*j+1] * f + gv * opos_s[d + 1]);
        }
    }
}

extern "C" void kernel_launch(void* const* d_in, const int* in_sizes, int n_in,
                              void* d_out, int out_size) {
    const float* x    = (const float*)d_in[0];
    const float* pos  = (const float*)d_in[1];
    const float* Wq   = (const float*)d_in[2];
    const float* Wk   = (const float*)d_in[3];
    const float* Wv   = (const float*)d_in[4];
    const float* Wo   = (const float*)d_in[5];
    const float* bo   = (const float*)d_in[6];
    const float* Wp1  = (const float*)d_in[7];
    const float* bp1  = (const float*)d_in[8];
    const float* Wp2  = (const float*)d_in[9];
    const float* bp2  = (const float*)d_in[10];
    const float* Wh   = (const float*)d_in[11];
    // d_in[12] = bh : cancels inside softmax — unused
    const float* gate = (const float*)d_in[13];
    float* out = (float*)d_out;

    u_kernel<<<8, 256>>>(pos, Wp1, bp1, Wp2, bp2, Wh);
    pos_w_kernel<<<32, 512>>>();
    split_w_kernel<<<2048, 256>>>(Wq, Wk, Wv, Wo);
    split_x_kernel<<<1024, 256>>>(x);
    qkv_mma<<<dim3(4, 16, 3), 256>>>();
    split_q_kernel<<<1024, 256>>>();
    split_kv_kernel<<<dim3(2048, 2), 256>>>();
    opos_kernel<<<dim3(32, 4), 256>>>();
    attn_mma<<<dim3(8, 32), 128>>>(gate);
    split_y_kernel<<<1024, 256>>>();
    out_mma<<<dim3(4, 16), 256>>>(bo, out);
}

// round 9
// speedup vs baseline: 1.4170x; 1.4170x over previous
#include <cuda_runtime.h>
#include <math.h>

#define NB 4
#define NS 512
#define NDIM 512
#define NH 8
#define NDH 64
#define NM (NB*NS)     // 2048

// ---------------- device scratch (no allocations allowed) ----------------
__device__ float g_q[NB*NH*NS*NDH];     // [b][h][s][d]
__device__ float g_k[NB*NH*NS*NDH];
__device__ float g_v[NB*NH*NS*NDH];
__device__ float g_u[NB*NS*NH];
__device__ float g_w[NB*NH*NS];
__device__ float g_opos[NB*NH*NDH];     // [b][h][d] : w @ V
__device__ float g_y[NM*NDIM];

// tf32 hi/lo pre-split fragment arrays (dense GEMMs)
__device__ float g_xh[NM*NDIM], g_xl[NM*NDIM];
__device__ float g_yh[NM*NDIM], g_yl[NM*NDIM];
__device__ float g_wh[4*NDIM*NDIM], g_wl[4*NDIM*NDIM];
// attention fragment arrays
// Q A-side: [bh][mblk(32)][kblk(8)][lane(32)][reg(4)]
__device__ float g_qfh[NB*NH*NS*NDH], g_qfl[NB*NH*NS*NDH];
// K B-side: [bh][kblk(8 dims)][nblk(64 pos)][lane(32)][reg(2)]
__device__ float g_kfh[NB*NH*NS*NDH], g_kfl[NB*NH*NS*NDH];
// V B-side: [bh][kposblk(64)][nblk(8 dh)][lane(32)][reg(2)]
__device__ float g_vfh[NB*NH*NS*NDH], g_vfl[NB*NH*NS*NDH];

__device__ __forceinline__ unsigned f2tf(float x) {
    unsigned r;
    asm("cvt.rna.tf32.f32 %0, %1;" : "=r"(r) : "f"(x));
    return r;
}

__device__ __forceinline__ void mma_tf32(float (&d)[4], const unsigned (&a)[4],
                                         unsigned b0, unsigned b1) {
    asm volatile(
        "mma.sync.aligned.m16n8k8.row.col.f32.tf32.tf32.f32 "
        "{%0,%1,%2,%3}, {%4,%5,%6,%7}, {%8,%9}, {%0,%1,%2,%3};"
        : "+f"(d[0]), "+f"(d[1]), "+f"(d[2]), "+f"(d[3])
        : "r"(a[0]), "r"(a[1]), "r"(a[2]), "r"(a[3]), "r"(b0), "r"(b1));
}

__device__ __forceinline__ unsigned cvta_sh(const void* p) {
    return (unsigned)__cvta_generic_to_shared(p);
}
#define CPA16(dst, src) \
    asm volatile("cp.async.cg.shared.global [%0], [%1], 16;" :: "r"(dst), "l"(src))

// ---------------- coalesced split kernels (dense GEMM operands) ----------
__device__ __forceinline__ void split_a2(const float* __restrict__ src,
                                         float* __restrict__ dh, float* __restrict__ dl) {
    int gw = blockIdx.x * 8 + (threadIdx.x >> 5);
    int lane = threadIdx.x & 31;
    int mblk = gw >> 6, kblk = gw & 63;
    float h[4], l[4];
    #pragma unroll
    for (int r = 0; r < 4; r++) {
        int mr = (lane >> 2) | ((r & 1) << 3);
        int kc = (lane & 3) | ((r >> 1) << 2);
        float v = src[(mblk * 16 + mr) * NDIM + kblk * 8 + kc];
        h[r] = __uint_as_float(f2tf(v));
        l[r] = __uint_as_float(f2tf(v - h[r]));
    }
    int idx = (gw * 32 + lane) * 4;
    *(float4*)&dh[idx] = make_float4(h[0], h[1], h[2], h[3]);
    *(float4*)&dl[idx] = make_float4(l[0], l[1], l[2], l[3]);
}
__global__ void split_x_kernel(const float* __restrict__ X) { split_a2(X, g_xh, g_xl); }
__global__ void split_y_kernel() { split_a2(g_y, g_yh, g_yl); }

__global__ void split_w_kernel(const float* __restrict__ Wq, const float* __restrict__ Wk,
                               const float* __restrict__ Wv, const float* __restrict__ Wo) {
    int gw = blockIdx.x * 8 + (threadIdx.x >> 5);
    int lane = threadIdx.x & 31;
    int mat = gw >> 12;
    int rem = gw & 4095;
    int kblk = rem >> 6, nblk = rem & 63;
    const float* W = (mat == 0) ? Wq : (mat == 1) ? Wk : (mat == 2) ? Wv : Wo;
    int nc = lane >> 2, tl = lane & 3;
    float h[2], l[2];
    #pragma unroll
    for (int r = 0; r < 2; r++) {
        int kc = tl | (r << 2);
        float v = W[(kblk * 8 + kc) * NDIM + nblk * 8 + nc];
        h[r] = __uint_as_float(f2tf(v));
        l[r] = __uint_as_float(f2tf(v - h[r]));
    }
    int idx = mat * NDIM * NDIM + (rem * 32 + lane) * 2;
    *(float2*)&g_wh[idx] = make_float2(h[0], h[1]);
    *(float2*)&g_wl[idx] = make_float2(l[0], l[1]);
}

// ---------------- attention fragment splits ----------------
__global__ void split_q_kernel() {
    int gw = blockIdx.x * 8 + (threadIdx.x >> 5);   // 0..8191
    int lane = threadIdx.x & 31;
    int bh = gw >> 8, rem = gw & 255;
    int mblk = rem >> 3, kblk = rem & 7;
    const float* Q = g_q + (size_t)bh * NS * NDH;
    int g = lane >> 2, t = lane & 3;
    float h[4], l[4];
    #pragma unroll
    for (int r = 0; r < 4; r++) {
        int mr = g | ((r & 1) << 3);
        int kc = t | ((r >> 1) << 2);
        float v = Q[(mblk * 16 + mr) * NDH + kblk * 8 + kc];
        h[r] = __uint_as_float(f2tf(v));
        l[r] = __uint_as_float(f2tf(v - h[r]));
    }
    size_t idx = ((size_t)gw * 32 + lane) * 4;
    *(float4*)&g_qfh[idx] = make_float4(h[0], h[1], h[2], h[3]);
    *(float4*)&g_qfl[idx] = make_float4(l[0], l[1], l[2], l[3]);
}

__global__ void split_kv_kernel() {
    int gw = blockIdx.x * 8 + (threadIdx.x >> 5);   // 0..16383
    int lane = threadIdx.x & 31;
    int nc = lane >> 2, t = lane & 3;
    int bh = gw >> 9, rem = gw & 511;
    if (blockIdx.y == 0) {
        int kblk = rem >> 6, nblk = rem & 63;
        const float* K = g_k + (size_t)bh * NS * NDH;
        float h[2], l[2];
        #pragma unroll
        for (int r = 0; r < 2; r++) {
            float v = K[(nblk * 8 + nc) * NDH + kblk * 8 + t + 4 * r];
            h[r] = __uint_as_float(f2tf(v));
            l[r] = __uint_as_float(f2tf(v - h[r]));
        }
        size_t idx = ((size_t)gw * 32 + lane) * 2;
        *(float2*)&g_kfh[idx] = make_float2(h[0], h[1]);
        *(float2*)&g_kfl[idx] = make_float2(l[0], l[1]);
    } else {
        int kposblk = rem >> 3, nblk = rem & 7;
        const float* V = g_v + (size_t)bh * NS * NDH;
        float h[2], l[2];
        #pragma unroll
        for (int r = 0; r < 2; r++) {
            float v = V[(kposblk * 8 + t + 4 * r) * NDH + nblk * 8 + nc];
            h[r] = __uint_as_float(f2tf(v));
            l[r] = __uint_as_float(f2tf(v - h[r]));
        }
        size_t idx = ((size_t)gw * 32 + lane) * 2;
        *(float2*)&g_vfh[idx] = make_float2(h[0], h[1]);
        *(float2*)&g_vfl[idx] = make_float2(l[0], l[1]);
    }
}

// =====================================================================
// tf32 x3 MMA GEMM, 128x128 tile, 8 warps, cp.async double-buffered smem.
// =====================================================================
__device__ __forceinline__ void mma_gemm_tile2(const float* __restrict__ Ah,
                                               const float* __restrict__ Al,
                                               const float* __restrict__ Bh,
                                               const float* __restrict__ Bl,
                                               int mblk0, int nblk0,
                                               float (&acc)[2][8][4], float* sm) {
    float* sAh = sm;
    float* sAl = sm + 2048;
    float* sBh = sm + 4096;
    float* sBl = sm + 6144;
    int tid = threadIdx.x, lane = tid & 31, wid = tid >> 5;
    int warp_m = wid >> 1, warp_n = wid & 1;
    int a_mblk = tid >> 5, a_lane = tid & 31;
    int b_nblk = tid >> 4, b_pair = (tid & 15) * 2;

    unsigned dAh = cvta_sh(&sAh[a_mblk * 128 + a_lane * 4]);
    unsigned dAl = cvta_sh(&sAl[a_mblk * 128 + a_lane * 4]);
    unsigned dBh = cvta_sh(&sBh[b_nblk * 64 + b_pair * 2]);
    unsigned dBl = cvta_sh(&sBl[b_nblk * 64 + b_pair * 2]);
    const float* srcAh = &Ah[((mblk0 + a_mblk) * 64) * 128 + a_lane * 4];
    const float* srcAl = &Al[((mblk0 + a_mblk) * 64) * 128 + a_lane * 4];
    const float* srcBh = &Bh[(nblk0 + b_nblk) * 64 + b_pair * 2];
    const float* srcBl = &Bl[(nblk0 + b_nblk) * 64 + b_pair * 2];

    auto issue = [&](int kb, int buf) {
        CPA16(dAh + buf * 4096, srcAh + kb * 128);
        CPA16(dAl + buf * 4096, srcAl + kb * 128);
        CPA16(dBh + buf * 4096, srcBh + (size_t)kb * 64 * 64);
        CPA16(dBl + buf * 4096, srcBl + (size_t)kb * 64 * 64);
        asm volatile("cp.async.commit_group;");
    };

    issue(0, 0);
    int buf = 0;
    for (int kb = 0; kb < 64; kb++) {
        if (kb < 63) {
            issue(kb + 1, buf ^ 1);
            asm volatile("cp.async.wait_group 1;");
        } else {
            asm volatile("cp.async.wait_group 0;");
        }
        __syncthreads();

        unsigned ah[2][4], al[2][4];
        #pragma unroll
        for (int mb2 = 0; mb2 < 2; mb2++) {
            float4 h4 = *(float4*)&sAh[buf * 1024 + (warp_m * 2 + mb2) * 128 + lane * 4];
            float4 l4 = *(float4*)&sAl[buf * 1024 + (warp_m * 2 + mb2) * 128 + lane * 4];
            ah[mb2][0] = __float_as_uint(h4.x); ah[mb2][1] = __float_as_uint(h4.y);
            ah[mb2][2] = __float_as_uint(h4.z); ah[mb2][3] = __float_as_uint(h4.w);
            al[mb2][0] = __float_as_uint(l4.x); al[mb2][1] = __float_as_uint(l4.y);
            al[mb2][2] = __float_as_uint(l4.z); al[mb2][3] = __float_as_uint(l4.w);
        }
        #pragma unroll
        for (int nb = 0; nb < 8; nb++) {
            float2 h2 = *(float2*)&sBh[buf * 1024 + (warp_n * 8 + nb) * 64 + lane * 2];
            float2 l2 = *(float2*)&sBl[buf * 1024 + (warp_n * 8 + nb) * 64 + lane * 2];
            unsigned b0h = __float_as_uint(h2.x), b1h = __float_as_uint(h2.y);
            unsigned b0l = __float_as_uint(l2.x), b1l = __float_as_uint(l2.y);
            #pragma unroll
            for (int mb2 = 0; mb2 < 2; mb2++) {
                mma_tf32(acc[mb2][nb], ah[mb2], b0h, b1h);
                mma_tf32(acc[mb2][nb], ah[mb2], b0l, b1l);
                mma_tf32(acc[mb2][nb], al[mb2], b0h, b1h);
            }
        }
        __syncthreads();
        buf ^= 1;
    }
}

__global__ void __launch_bounds__(256, 2)
qkv_mma() {
    __shared__ float sm[8192];
    int mat = blockIdx.z;
    float* out = (mat == 0) ? g_q : (mat == 1) ? g_k : g_v;
    const float* Bh = g_wh + mat * NDIM * NDIM;
    const float* Bl = g_wl + mat * NDIM * NDIM;
    int m0 = blockIdx.y * 128, n0 = blockIdx.x * 128;
    float acc[2][8][4] = {};
    mma_gemm_tile2(g_xh, g_xl, Bh, Bl, m0 >> 4, n0 >> 3, acc, sm);

    int lane = threadIdx.x & 31, wid = threadIdx.x >> 5;
    int warp_m = wid >> 1, warp_n = wid & 1;
    int g = lane >> 2, t = lane & 3;
    #pragma unroll
    for (int mb2 = 0; mb2 < 2; mb2++) {
        int mrow = m0 + warp_m * 32 + mb2 * 16 + g;
        #pragma unroll
        for (int nb = 0; nb < 8; nb++) {
            int ncol = n0 + (warp_n * 8 + nb) * 8 + 2 * t;
            int h = ncol >> 6, d = ncol & 63;
            {
                int b = mrow >> 9, s = mrow & 511;
                *(float2*)&out[((b * NH + h) * NS + s) * NDH + d] =
                    make_float2(acc[mb2][nb][0], acc[mb2][nb][1]);
            }
            {
                int m2 = mrow + 8;
                int b = m2 >> 9, s = m2 & 511;
                *(float2*)&out[((b * NH + h) * NS + s) * NDH + d] =
                    make_float2(acc[mb2][nb][2], acc[mb2][nb][3]);
            }
        }
    }
}

__global__ void __launch_bounds__(256, 2)
out_mma(const float* __restrict__ bo, float* __restrict__ out) {
    __shared__ float sm[8192];
    const float* Bh = g_wh + 3 * NDIM * NDIM;
    const float* Bl = g_wl + 3 * NDIM * NDIM;
    int m0 = blockIdx.y * 128, n0 = blockIdx.x * 128;
    float acc[2][8][4] = {};
    mma_gemm_tile2(g_yh, g_yl, Bh, Bl, m0 >> 4, n0 >> 3, acc, sm);

    int lane = threadIdx.x & 31, wid = threadIdx.x >> 5;
    int warp_m = wid >> 1, warp_n = wid & 1;
    int g = lane >> 2, t = lane & 3;
    #pragma unroll
    for (int mb2 = 0; mb2 < 2; mb2++) {
        int mrow = m0 + warp_m * 32 + mb2 * 16 + g;
        #pragma unroll
        for (int nb = 0; nb < 8; nb++) {
            int ncol = n0 + (warp_n * 8 + nb) * 8 + 2 * t;
            float b0 = bo[ncol], b1 = bo[ncol + 1];
            *(float2*)&out[(size_t)mrow * NDIM + ncol] =
                make_float2(acc[mb2][nb][0] + b0, acc[mb2][nb][1] + b1);
            *(float2*)&out[(size_t)(mrow + 8) * NDIM + ncol] =
                make_float2(acc[mb2][nb][2] + b0, acc[mb2][nb][3] + b1);
        }
    }
}

// ---------------- tiny positional MLP ----------------
__global__ void u_kernel(const float* __restrict__ pos,
                         const float* __restrict__ Wp1, const float* __restrict__ bp1,
                         const float* __restrict__ Wp2, const float* __restrict__ bp2,
                         const float* __restrict__ Wh) {
    int idx = blockIdx.x * blockDim.x + threadIdx.x;
    if (idx >= NM) return;
    g_opos[idx & (NB*NH*NDH - 1)] = 0.0f;
    const float* pp = pos + idx * 3;
    float p0 = pp[0], p1 = pp[1], p2 = pp[2];
    float h1[3];
    #pragma unroll
    for (int j = 0; j < 3; j++)
        h1[j] = fmaxf(0.0f, p0 * Wp1[j] + p1 * Wp1[3 + j] + p2 * Wp1[6 + j] + bp1[j]);
    float u[NH];
    #pragma unroll
    for (int hh = 0; hh < NH; hh++) u[hh] = 0.0f;
    for (int j = 0; j < 64; j++) {
        float pv = h1[0] * Wp2[j] + h1[1] * Wp2[64 + j] + h1[2] * Wp2[128 + j] + bp2[j];
        #pragma unroll
        for (int hh = 0; hh < NH; hh++) u[hh] += pv * Wh[j * NH + hh];
    }
    #pragma unroll
    for (int hh = 0; hh < NH; hh++) g_u[idx * NH + hh] = u[hh];
}

__global__ void pos_w_kernel() {
    __shared__ float red[512];
    int bh = blockIdx.x;
    int b = bh >> 3, h = bh & 7;
    int k = threadIdx.x;
    float t = -g_u[(b * NS + k) * NH + h];
    red[k] = t; __syncthreads();
    for (int s = 256; s > 0; s >>= 1) { if (k < s) red[k] = fmaxf(red[k], red[k + s]); __syncthreads(); }
    float m = red[0]; __syncthreads();
    float e = expf(t - m);
    red[k] = e; __syncthreads();
    for (int s = 256; s > 0; s >>= 1) { if (k < s) red[k] += red[k + s]; __syncthreads(); }
    g_w[bh * NS + k] = e / red[0];
}

__global__ void opos_kernel() {
    __shared__ float part[4][64];
    int bh = blockIdx.x;
    int kq = blockIdx.y;
    int d = threadIdx.x & 63;
    int ks = threadIdx.x >> 6;
    const float* V = g_v + (size_t)bh * NS * NDH;
    const float* w = g_w + bh * NS;
    int kbase = kq * 128 + ks * 32;
    float s = 0.0f;
    #pragma unroll 4
    for (int k = kbase; k < kbase + 32; k++)
        s += w[k] * V[k * NDH + d];
    part[ks][d] = s;
    __syncthreads();
    if (threadIdx.x < 64)
        atomicAdd(&g_opos[bh * NDH + d], part[0][d] + part[1][d] + part[2][d] + part[3][d]);
}

// =====================================================================
// tf32 mma flash attention v2: K/V fragments staged in smem via cp.async,
// shared across 4 warps. Warp owns m16; P round-trip warp-private.
// smem: sKh/sKl/sVh/sVl 4096 floats each + Ps[64][68] + opos[64] = 83,200 B
// =====================================================================
#define ATTN_SMEM_FLOATS (16384 + 64*68 + 64)
#define ATTN_SMEM_BYTES  (ATTN_SMEM_FLOATS * 4)

__global__ void __launch_bounds__(128, 2)
attn_mma(const float* __restrict__ gate) {
    extern __shared__ float asm_[];
    float* sKh = asm_;
    float* sKl = asm_ + 4096;
    float* sVh = asm_ + 8192;
    float* sVl = asm_ + 12288;
    float (*Ps)[68] = (float(*)[68])(asm_ + 16384);
    float* opos_s = asm_ + 16384 + 64 * 68;

    int tid = threadIdx.x, lane = tid & 31, w = tid >> 5;
    int bh = blockIdx.y, q0 = blockIdx.x * 64;
    int h = bh & 7, b = bh >> 3;
    int g = lane >> 2, t = lane & 3;
    int mblk = (q0 >> 4) + w;
    int rowbase = w * 16;

    float gv = 1.0f / (1.0f + __expf(-gate[h]));
    float og = 1.0f - gv;
    if (tid < 64) opos_s[tid] = g_opos[bh * NDH + tid];

    const float* kfh = g_kfh + (size_t)bh * 32768;
    const float* kfl = g_kfl + (size_t)bh * 32768;
    const float* vfh = g_vfh + (size_t)bh * 32768;
    const float* vfl = g_vfl + (size_t)bh * 32768;

    // stage chunk kc into smem (4096 floats per array)
    auto stage = [&](int kc) {
        #pragma unroll
        for (int r = 0; r < 8; r++) {
            int i = (r * 128 + tid) * 4;          // 0..4095, float4 aligned
            int kb = i >> 9, rem = i & 511;
            size_t koff = (size_t)(kb * 64 + kc * 8) * 64 + rem;
            CPA16(cvta_sh(&sKh[i]), kfh + koff);
            CPA16(cvta_sh(&sKl[i]), kfl + koff);
            size_t voff = (size_t)kc * 4096 + i;
            CPA16(cvta_sh(&sVh[i]), vfh + voff);
            CPA16(cvta_sh(&sVl[i]), vfl + voff);
        }
        asm volatile("cp.async.commit_group;");
    };

    // Q fragments hoisted
    unsigned aqh[8][4], aql[8][4];
    {
        const float* qh = g_qfh + ((size_t)(bh * 32 + mblk) * 8) * 128;
        const float* ql = g_qfl + ((size_t)(bh * 32 + mblk) * 8) * 128;
        #pragma unroll
        for (int kb = 0; kb < 8; kb++) {
            float4 hv = *(const float4*)&qh[kb * 128 + lane * 4];
            float4 lv = *(const float4*)&ql[kb * 128 + lane * 4];
            aqh[kb][0] = __float_as_uint(hv.x); aqh[kb][1] = __float_as_uint(hv.y);
            aqh[kb][2] = __float_as_uint(hv.z); aqh[kb][3] = __float_as_uint(hv.w);
            aql[kb][0] = __float_as_uint(lv.x); aql[kb][1] = __float_as_uint(lv.y);
            aql[kb][2] = __float_as_uint(lv.z); aql[kb][3] = __float_as_uint(lv.w);
        }
    }

    stage(0);

    float o[8][4] = {};
    float mrow[2] = {-1e30f, -1e30f};
    float lrow[2] = {0.0f, 0.0f};

    for (int kc = 0; kc < 8; kc++) {
        asm volatile("cp.async.wait_group 0;");
        __syncthreads();

        // ---- S chunk = Q K^T, 3-split tf32, K from smem ----
        float sacc[8][4] = {};
        #pragma unroll
        for (int kb = 0; kb < 8; kb++) {
            #pragma unroll
            for (int nb = 0; nb < 8; nb++) {
                int off = (kb * 512 + nb * 64) + lane * 2;
                float2 h2 = *(float2*)&sKh[off];
                float2 l2 = *(float2*)&sKl[off];
                unsigned b0h = __float_as_uint(h2.x), b1h = __float_as_uint(h2.y);
                unsigned b0l = __float_as_uint(l2.x), b1l = __float_as_uint(l2.y);
                mma_tf32(sacc[nb], aqh[kb], b0h, b1h);
                mma_tf32(sacc[nb], aqh[kb], b0l, b1l);
                mma_tf32(sacc[nb], aql[kb], b0h, b1h);
            }
        }
        // ---- online softmax ----
        #pragma unroll
        for (int j = 0; j < 2; j++) {
            float mx = -1e30f;
            #pragma unroll
            for (int nb = 0; nb < 8; nb++)
                mx = fmaxf(mx, fmaxf(sacc[nb][2*j], sacc[nb][2*j+1]));
            mx *= 0.125f;
            mx = fmaxf(mx, __shfl_xor_sync(0xFFFFFFFF, mx, 1));
            mx = fmaxf(mx, __shfl_xor_sync(0xFFFFFFFF, mx, 2));
            float mn = fmaxf(mrow[j], mx);
            float alpha = __expf(mrow[j] - mn);
            float rs = 0.0f;
            #pragma unroll
            for (int nb = 0; nb < 8; nb++) {
                float p0 = __expf(sacc[nb][2*j] * 0.125f - mn);
                float p1 = __expf(sacc[nb][2*j+1] * 0.125f - mn);
                sacc[nb][2*j] = p0; sacc[nb][2*j+1] = p1;
                rs += p0 + p1;
            }
            rs += __shfl_xor_sync(0xFFFFFFFF, rs, 1);
            rs += __shfl_xor_sync(0xFFFFFFFF, rs, 2);
            lrow[j] = lrow[j] * alpha + rs;
            mrow[j] = mn;
            #pragma unroll
            for (int nb = 0; nb < 8; nb++) { o[nb][2*j] *= alpha; o[nb][2*j+1] *= alpha; }
        }
        // ---- P c-layout -> warp-private smem strip ----
        __syncwarp();
        #pragma unroll
        for (int nb = 0; nb < 8; nb++) {
            *(float2*)&Ps[rowbase + g][nb * 8 + 2 * t]     = make_float2(sacc[nb][0], sacc[nb][1]);
            *(float2*)&Ps[rowbase + g + 8][nb * 8 + 2 * t] = make_float2(sacc[nb][2], sacc[nb][3]);
        }
        __syncwarp();
        // ---- O += P @ V (3-split), V from smem ----
        #pragma unroll
        for (int kb = 0; kb < 8; kb++) {
            float p0 = Ps[rowbase + g][kb * 8 + t];
            float p1 = Ps[rowbase + g + 8][kb * 8 + t];
            float p2 = Ps[rowbase + g][kb * 8 + t + 4];
            float p3 = Ps[rowbase + g + 8][kb * 8 + t + 4];
            unsigned ph[4], pl[4];
            ph[0] = f2tf(p0); pl[0] = f2tf(p0 - __uint_as_float(ph[0]));
            ph[1] = f2tf(p1); pl[1] = f2tf(p1 - __uint_as_float(ph[1]));
            ph[2] = f2tf(p2); pl[2] = f2tf(p2 - __uint_as_float(ph[2]));
            ph[3] = f2tf(p3); pl[3] = f2tf(p3 - __uint_as_float(ph[3]));
            #pragma unroll
            for (int nb = 0; nb < 8; nb++) {
                int off = (kb * 512 + nb * 64) + lane * 2;
                float2 h2 = *(float2*)&sVh[off];
                float2 l2 = *(float2*)&sVl[off];
                unsigned b0h = __float_as_uint(h2.x), b1h = __float_as_uint(h2.y);
                unsigned b0l = __float_as_uint(l2.x), b1l = __float_as_uint(l2.y);
                mma_tf32(o[nb], ph, b0h, b1h);
                mma_tf32(o[nb], ph, b0l, b1l);
                mma_tf32(o[nb], pl, b0h, b1h);
            }
        }
        __syncthreads();
        if (kc < 7) stage(kc + 1);
    }

    // ---- epilogue: out = og * o / l + gv * O_pos ----
    #pragma unroll
    for (int j = 0; j < 2; j++) {
        int q = q0 + rowbase + g + j * 8;
        float f = og / lrow[j];
        #pragma unroll
        for (int nb = 0; nb < 8; nb++) {
            int d = nb * 8 + 2 * t;
            *(float2*)&g_y[((size_t)b * NS + q) * NDIM + h * NDH + d] =
                make_float2(o[nb][2*j] * f + gv * opos_s[d],
                            o[nb][2*j+1] * f + gv * opos_s[d + 1]);
        }
    }
}

extern "C" void kernel_launch(void* const* d_in, const int* in_sizes, int n_in,
                              void* d_out, int out_size) {
    const float* x    = (const float*)d_in[0];
    const float* pos  = (const float*)d_in[1];
    const float* Wq   = (const float*)d_in[2];
    const float* Wk   = (const float*)d_in[3];
    const float* Wv   = (const float*)d_in[4];
    const float* Wo   = (const float*)d_in[5];
    const float* bo   = (const float*)d_in[6];
    const float* Wp1  = (const float*)d_in[7];
    const float* bp1  = (const float*)d_in[8];
    const float* Wp2  = (const float*)d_in[9];
    const float* bp2  = (const float*)d_in[10];
    const float* Wh   = (const float*)d_in[11];
    // d_in[12] = bh : cancels inside softmax — unused
    const float* gate = (const float*)d_in[13];
    float* out = (float*)d_out;

    static bool attr_set = false;
    if (!attr_set) {
        cudaFuncSetAttribute(attn_mma, cudaFuncAttributeMaxDynamicSharedMemorySize, ATTN_SMEM_BYTES);
        attr_set = true;
    }

    u_kernel<<<8, 256>>>(pos, Wp1, bp1, Wp2, bp2, Wh);
    pos_w_kernel<<<32, 512>>>();
    split_w_kernel<<<2048, 256>>>(Wq, Wk, Wv, Wo);
    split_x_kernel<<<1024, 256>>>(x);
    qkv_mma<<<dim3(4, 16, 3), 256>>>();
    split_q_kernel<<<1024, 256>>>();
    split_kv_kernel<<<dim3(2048, 2), 256>>>();
    opos_kernel<<<dim3(32, 4), 256>>>();
    attn_mma<<<dim3(8, 32), 128, ATTN_SMEM_BYTES>>>(gate);
    split_y_kernel<<<1024, 256>>>();
    out_mma<<<dim3(4, 16), 256>>>(bo, out);
}